// round 6
// baseline (speedup 1.0000x reference)
#include <cuda_runtime.h>

#define IN_DIM   8192
#define OUT_DIM  8192
#define TPB      256
#define VPT      (IN_DIM / 4 / TPB)   // float4 per thread per row = 8
#define THRESH   50.0f
#define NBLOCKS  912                  // 152 SMs * 6 resident CTAs -> single wave

__global__ __launch_bounds__(TPB)
void snn_fused_kernel(const float* __restrict__ spike_input,
                      const float* __restrict__ states,
                      const float* __restrict__ v_mem,
                      const float* __restrict__ v_th,
                      const float* __restrict__ elig,
                      const float* __restrict__ noise,
                      float* __restrict__ out)
{
    __shared__ float s_spike[IN_DIM];      // 32 KB, staged once per block
    __shared__ float s_warp[TPB / 32];
    __shared__ float s_spk;

    const int tid = threadIdx.x;

    // ---- stage spike_input once, reused for ~9 rows ----
    const float4* sp4 = reinterpret_cast<const float4*>(spike_input);
    float4* ss4 = reinterpret_cast<float4*>(s_spike);
    #pragma unroll
    for (int it = 0; it < VPT; ++it)
        ss4[it * TPB + tid] = sp4[it * TPB + tid];
    __syncthreads();

    for (int row = blockIdx.x; row < OUT_DIM; row += NBLOCKS) {
        const float4* st4  = reinterpret_cast<const float4*>(states + (size_t)row * IN_DIM);
        const float4* el4  = reinterpret_cast<const float4*>(elig   + (size_t)row * IN_DIM);
        float4*       out4 = reinterpret_cast<float4*>(out + 3 * (size_t)OUT_DIM + (size_t)row * IN_DIM);

        // ---- phase 1: binary-weight GEMV dot product ----
        float acc = 0.0f;
        #pragma unroll
        for (int it = 0; it < VPT; ++it) {
            const int i = it * TPB + tid;
            float4 s  = __ldcs(&st4[i]);     // read-once stream
            float4 sp = ss4[i];
            if (s.x > THRESH) acc += sp.x;
            if (s.y > THRESH) acc += sp.y;
            if (s.z > THRESH) acc += sp.z;
            if (s.w > THRESH) acc += sp.w;
        }

        // ---- block reduction ----
        #pragma unroll
        for (int off = 16; off > 0; off >>= 1)
            acc += __shfl_xor_sync(0xFFFFFFFFu, acc, off);
        if ((tid & 31) == 0) s_warp[tid >> 5] = acc;
        __syncthreads();

        if (tid == 0) {
            float total = 0.0f;
            #pragma unroll
            for (int w = 0; w < TPB / 32; ++w) total += s_warp[w];

            const float vth   = v_th[row];
            const float v_new = v_mem[row] * 0.8f + total + noise[row];
            const float spk   = (v_new >= vth) ? 1.0f : 0.0f;

            // outputs: [spikes | v_mem_new | v_th_new | elig_new]
            out[row]           = spk;
            out[OUT_DIM + row] = v_new * (1.0f - spk) * 0.2f;
            float vth_new = vth + (spk - 0.05f) * 0.1f;
            out[2 * OUT_DIM + row] = fminf(fmaxf(vth_new, 0.5f), 10.0f);

            s_spk = spk;
        }
        __syncthreads();

        // ---- phase 2: eligibility trace update ----
        const float spk = s_spk;
        #pragma unroll
        for (int it = 0; it < VPT; ++it) {
            const int i = it * TPB + tid;
            float4 e  = __ldcs(&el4[i]);     // read-once stream
            float4 sp = ss4[i];
            float4 r;
            r.x = fminf(fmaxf(fmaf(e.x, 0.95f, spk * sp.x), 0.0f), 5.0f);
            r.y = fminf(fmaxf(fmaf(e.y, 0.95f, spk * sp.y), 0.0f), 5.0f);
            r.z = fminf(fmaxf(fmaf(e.z, 0.95f, spk * sp.z), 0.0f), 5.0f);
            r.w = fminf(fmaxf(fmaf(e.w, 0.95f, spk * sp.w), 0.0f), 5.0f);
            __stcs(&out4[i], r);
        }
        // no barrier needed here: s_spk is re-written only after the next
        // row's reduction __syncthreads(), and s_spike is read-only.
        __syncthreads();   // protect s_warp/s_spk reuse across iterations
    }
}

extern "C" void kernel_launch(void* const* d_in, const int* in_sizes, int n_in,
                              void* d_out, int out_size)
{
    const float* spike_input = (const float*)d_in[0];
    const float* states      = (const float*)d_in[1];
    const float* v_mem       = (const float*)d_in[2];
    const float* v_th        = (const float*)d_in[3];
    const float* elig        = (const float*)d_in[4];
    const float* noise       = (const float*)d_in[5];
    float* out = (float*)d_out;

    snn_fused_kernel<<<NBLOCKS, TPB>>>(spike_input, states, v_mem, v_th,
                                       elig, noise, out);
}

// round 7
// speedup vs baseline: 1.2976x; 1.2976x over previous
#include <cuda_runtime.h>

#define IN_DIM   8192
#define OUT_DIM  8192
#define TPB      256
#define VPT      (IN_DIM / 4 / TPB)   // float4 per thread per row = 8
#define THRESH   50.0f

// ---------------- kernel 1: GEMV + neuron dynamics (pure READ stream) ----------------
__global__ __launch_bounds__(TPB)
void snn_gemv_kernel(const float* __restrict__ spike_input,
                     const float* __restrict__ states,
                     const float* __restrict__ v_mem,
                     const float* __restrict__ v_th,
                     const float* __restrict__ noise,
                     float* __restrict__ out)
{
    __shared__ float s_warp[TPB / 32];

    const int row = blockIdx.x;
    const int tid = threadIdx.x;

    const float4* sp4 = reinterpret_cast<const float4*>(spike_input);
    const float4* st4 = reinterpret_cast<const float4*>(states + (size_t)row * IN_DIM);

    float acc = 0.0f;
    #pragma unroll
    for (int it = 0; it < VPT; ++it) {
        const int i = it * TPB + tid;
        float4 s  = __ldcs(&st4[i]);
        float4 sp = __ldg(&sp4[i]);
        if (s.x > THRESH) acc += sp.x;
        if (s.y > THRESH) acc += sp.y;
        if (s.z > THRESH) acc += sp.z;
        if (s.w > THRESH) acc += sp.w;
    }

    #pragma unroll
    for (int off = 16; off > 0; off >>= 1)
        acc += __shfl_xor_sync(0xFFFFFFFFu, acc, off);
    if ((tid & 31) == 0) s_warp[tid >> 5] = acc;
    __syncthreads();

    if (tid == 0) {
        float total = 0.0f;
        #pragma unroll
        for (int w = 0; w < TPB / 32; ++w) total += s_warp[w];

        const float vth   = v_th[row];
        const float v_new = v_mem[row] * 0.8f + total + noise[row];
        const float spk   = (v_new >= vth) ? 1.0f : 0.0f;

        out[row]           = spk;                       // spikes
        out[OUT_DIM + row] = v_new * (1.0f - spk) * 0.2f;
        float vth_new = vth + (spk - 0.05f) * 0.1f;
        out[2 * OUT_DIM + row] = fminf(fmaxf(vth_new, 0.5f), 10.0f);
    }
}

// ---------------- kernel 2: eligibility trace (pure streaming, no barriers) ----------------
__global__ __launch_bounds__(TPB)
void snn_elig_kernel(const float* __restrict__ spike_input,
                     const float* __restrict__ elig,
                     const float* __restrict__ spikes,   // = out[0..OUT_DIM)
                     float* __restrict__ elig_out)
{
    const int row = blockIdx.x;
    const int tid = threadIdx.x;

    const float spk = __ldg(&spikes[row]);   // L2-resident 32 KB vector

    const float4* sp4  = reinterpret_cast<const float4*>(spike_input);
    const float4* el4  = reinterpret_cast<const float4*>(elig + (size_t)row * IN_DIM);
    float4*       out4 = reinterpret_cast<float4*>(elig_out + (size_t)row * IN_DIM);

    #pragma unroll
    for (int it = 0; it < VPT; ++it) {
        const int i = it * TPB + tid;
        float4 e  = __ldcs(&el4[i]);
        float4 sp = __ldg(&sp4[i]);
        float4 r;
        r.x = fminf(fmaxf(fmaf(e.x, 0.95f, spk * sp.x), 0.0f), 5.0f);
        r.y = fminf(fmaxf(fmaf(e.y, 0.95f, spk * sp.y), 0.0f), 5.0f);
        r.z = fminf(fmaxf(fmaf(e.z, 0.95f, spk * sp.z), 0.0f), 5.0f);
        r.w = fminf(fmaxf(fmaf(e.w, 0.95f, spk * sp.w), 0.0f), 5.0f);
        __stcs(&out4[i], r);
    }
}

extern "C" void kernel_launch(void* const* d_in, const int* in_sizes, int n_in,
                              void* d_out, int out_size)
{
    const float* spike_input = (const float*)d_in[0];
    const float* states      = (const float*)d_in[1];
    const float* v_mem       = (const float*)d_in[2];
    const float* v_th        = (const float*)d_in[3];
    const float* elig        = (const float*)d_in[4];
    const float* noise       = (const float*)d_in[5];
    float* out = (float*)d_out;

    // kernel 1 writes spikes/v_mem/v_th; kernel 2 (stream-ordered after it)
    // consumes out[0..OUT_DIM) as the spike vector.
    snn_gemv_kernel<<<OUT_DIM, TPB>>>(spike_input, states, v_mem, v_th, noise, out);
    snn_elig_kernel<<<OUT_DIM, TPB>>>(spike_input, elig, out,
                                      out + 3 * (size_t)OUT_DIM);
}

// round 8
// speedup vs baseline: 1.3652x; 1.0521x over previous
#include <cuda_runtime.h>

#define IN_DIM   8192
#define OUT_DIM  8192
#define TPB      256
#define VPT      (IN_DIM / 4 / TPB)   // float4 per thread per row = 8
#define THRESH   50.0f

__global__ __launch_bounds__(TPB)
void snn_fused2_kernel(const float* __restrict__ spike_input,
                       const float* __restrict__ states,
                       const float* __restrict__ v_mem,
                       const float* __restrict__ v_th,
                       const float* __restrict__ elig,
                       const float* __restrict__ noise,
                       float* __restrict__ out)
{
    __shared__ float s_warp0[TPB / 32];
    __shared__ float s_warp1[TPB / 32];
    __shared__ float s_spk0, s_spk1;

    const int r0  = blockIdx.x * 2;
    const int r1  = r0 + 1;
    const int tid = threadIdx.x;

    const float4* sp4  = reinterpret_cast<const float4*>(spike_input);
    const float4* st0  = reinterpret_cast<const float4*>(states + (size_t)r0 * IN_DIM);
    const float4* st1  = reinterpret_cast<const float4*>(states + (size_t)r1 * IN_DIM);
    const float4* el0  = reinterpret_cast<const float4*>(elig   + (size_t)r0 * IN_DIM);
    const float4* el1  = reinterpret_cast<const float4*>(elig   + (size_t)r1 * IN_DIM);
    float4* out0 = reinterpret_cast<float4*>(out + 3 * (size_t)OUT_DIM + (size_t)r0 * IN_DIM);
    float4* out1 = reinterpret_cast<float4*>(out + 3 * (size_t)OUT_DIM + (size_t)r1 * IN_DIM);

    // ---- phase 1: two-row GEMV (64 KB pure-read phase) ----
    float acc0 = 0.0f, acc1 = 0.0f;
    #pragma unroll
    for (int it = 0; it < VPT; ++it) {
        const int i = it * TPB + tid;
        float4 a  = __ldcs(&st0[i]);
        float4 b  = __ldcs(&st1[i]);
        float4 sp = __ldg(&sp4[i]);
        if (a.x > THRESH) acc0 += sp.x;
        if (a.y > THRESH) acc0 += sp.y;
        if (a.z > THRESH) acc0 += sp.z;
        if (a.w > THRESH) acc0 += sp.w;
        if (b.x > THRESH) acc1 += sp.x;
        if (b.y > THRESH) acc1 += sp.y;
        if (b.z > THRESH) acc1 += sp.z;
        if (b.w > THRESH) acc1 += sp.w;
    }

    // ---- one reduction barrier for both rows ----
    #pragma unroll
    for (int off = 16; off > 0; off >>= 1) {
        acc0 += __shfl_xor_sync(0xFFFFFFFFu, acc0, off);
        acc1 += __shfl_xor_sync(0xFFFFFFFFu, acc1, off);
    }
    if ((tid & 31) == 0) {
        s_warp0[tid >> 5] = acc0;
        s_warp1[tid >> 5] = acc1;
    }
    __syncthreads();

    if (tid == 0) {
        float t0 = 0.0f, t1 = 0.0f;
        #pragma unroll
        for (int w = 0; w < TPB / 32; ++w) { t0 += s_warp0[w]; t1 += s_warp1[w]; }

        const float vth0 = v_th[r0], vth1 = v_th[r1];
        const float v0 = v_mem[r0] * 0.8f + t0 + noise[r0];
        const float v1 = v_mem[r1] * 0.8f + t1 + noise[r1];
        const float k0 = (v0 >= vth0) ? 1.0f : 0.0f;
        const float k1 = (v1 >= vth1) ? 1.0f : 0.0f;

        // outputs: [spikes | v_mem_new | v_th_new | elig_new]
        out[r0] = k0;  out[r1] = k1;
        out[OUT_DIM + r0] = v0 * (1.0f - k0) * 0.2f;
        out[OUT_DIM + r1] = v1 * (1.0f - k1) * 0.2f;
        float n0 = vth0 + (k0 - 0.05f) * 0.1f;
        float n1 = vth1 + (k1 - 0.05f) * 0.1f;
        out[2 * OUT_DIM + r0] = fminf(fmaxf(n0, 0.5f), 10.0f);
        out[2 * OUT_DIM + r1] = fminf(fmaxf(n1, 0.5f), 10.0f);

        s_spk0 = k0;  s_spk1 = k1;
    }
    __syncthreads();

    // ---- phase 2: two-row eligibility update (128 KB r/w phase) ----
    const float k0 = s_spk0;
    const float k1 = s_spk1;
    #pragma unroll
    for (int it = 0; it < VPT; ++it) {
        const int i = it * TPB + tid;
        float4 e0 = __ldcs(&el0[i]);
        float4 e1 = __ldcs(&el1[i]);
        float4 sp = __ldg(&sp4[i]);   // L1/L2 hit
        float4 a, b;
        a.x = fminf(fmaxf(fmaf(e0.x, 0.95f, k0 * sp.x), 0.0f), 5.0f);
        a.y = fminf(fmaxf(fmaf(e0.y, 0.95f, k0 * sp.y), 0.0f), 5.0f);
        a.z = fminf(fmaxf(fmaf(e0.z, 0.95f, k0 * sp.z), 0.0f), 5.0f);
        a.w = fminf(fmaxf(fmaf(e0.w, 0.95f, k0 * sp.w), 0.0f), 5.0f);
        b.x = fminf(fmaxf(fmaf(e1.x, 0.95f, k1 * sp.x), 0.0f), 5.0f);
        b.y = fminf(fmaxf(fmaf(e1.y, 0.95f, k1 * sp.y), 0.0f), 5.0f);
        b.z = fminf(fmaxf(fmaf(e1.z, 0.95f, k1 * sp.z), 0.0f), 5.0f);
        b.w = fminf(fmaxf(fmaf(e1.w, 0.95f, k1 * sp.w), 0.0f), 5.0f);
        __stcs(&out0[i], a);
        __stcs(&out1[i], b);
    }
}

extern "C" void kernel_launch(void* const* d_in, const int* in_sizes, int n_in,
                              void* d_out, int out_size)
{
    const float* spike_input = (const float*)d_in[0];
    const float* states      = (const float*)d_in[1];
    const float* v_mem       = (const float*)d_in[2];
    const float* v_th        = (const float*)d_in[3];
    const float* elig        = (const float*)d_in[4];
    const float* noise       = (const float*)d_in[5];
    float* out = (float*)d_out;

    snn_fused2_kernel<<<OUT_DIM / 2, TPB>>>(spike_input, states, v_mem, v_th,
                                            elig, noise, out);
}